// round 2
// baseline (speedup 1.0000x reference)
#include <cuda_runtime.h>
#include <cuda_bf16.h>
#include <cstdint>

// Pseudo-random interleaver: out[b, l] = x[b, perm[b, l]]
// B = 1024 rows, L = 16384 elements/row, fp32.
// Strategy: one CTA per row. Stage the 64KB row into shared memory with
// coalesced float4 loads, then gather from smem (cheap random LDS) while
// reading perm and writing out fully coalesced as int4/float4.

#define ROW_LEN 16384
#define THREADS 512
#define VEC_ITERS (ROW_LEN / 4 / THREADS)   // 8

__global__ __launch_bounds__(THREADS) void interleaver_kernel(
    const float* __restrict__ x,
    const int*   __restrict__ perm,
    float*       __restrict__ out)
{
    extern __shared__ float srow[];   // 16384 floats = 64KB

    const int b   = blockIdx.x;
    const int tid = threadIdx.x;
    const size_t row_off = (size_t)b * ROW_LEN;

    // ---- Stage x row into shared memory (coalesced 16B loads/stores) ----
    const float4* __restrict__ x4 = (const float4*)(x + row_off);
    float4* s4 = (float4*)srow;
    #pragma unroll
    for (int i = 0; i < VEC_ITERS; i++) {
        s4[tid + i * THREADS] = x4[tid + i * THREADS];
    }
    __syncthreads();

    // ---- Gather: coalesced perm reads (int4), random smem reads, coalesced out writes ----
    const int4* __restrict__ p4 = (const int4*)(perm + row_off);
    float4* __restrict__ o4 = (float4*)(out + row_off);
    #pragma unroll
    for (int i = 0; i < VEC_ITERS; i++) {
        int4 p = p4[tid + i * THREADS];
        float4 v;
        v.x = srow[p.x];
        v.y = srow[p.y];
        v.z = srow[p.z];
        v.w = srow[p.w];
        o4[tid + i * THREADS] = v;
    }
}

extern "C" void kernel_launch(void* const* d_in, const int* in_sizes, int n_in,
                              void* d_out, int out_size)
{
    const float* x    = (const float*)d_in[0];
    const int*   perm = (const int*)d_in[1];
    float*       out  = (float*)d_out;

    const int B = in_sizes[1] / ROW_LEN;          // 1024
    const int smem_bytes = ROW_LEN * sizeof(float);  // 65536

    // >48KB dynamic smem requires opt-in (idempotent; safe to call every launch).
    cudaFuncSetAttribute(interleaver_kernel,
                         cudaFuncAttributeMaxDynamicSharedMemorySize, smem_bytes);

    interleaver_kernel<<<B, THREADS, smem_bytes>>>(x, perm, out);
}